// round 14
// baseline (speedup 1.0000x reference)
#include <cuda_runtime.h>
#include <cuda_bf16.h>

// Seq2SeqLoss: label-smoothed weighted cross-entropy, mean over masked rows.
// Harness canonical dtypes:
//   [0] outputs  f32 [B*S*C] = 131072000
//   [1] gold     i32 [B*S]   = 4096
//   [2] mask     i32 [B*S]   = 4096
//   [3] weight   f32 [C]     = 32000
// output: f32 scalar
//
// Sum factorization: with lse_r = log(sum_c exp(x_rc)), dd_r = sum_c w_c x_rc,
//   sum_r loss_r = uniform*(sumW*Σlse − Σdd) + (conf−uniform)*Σ w_g (lse − x_g)
//
// Schedule (R14): hardware CTA scheduling beat every persistent/software
// schedule (R11-R13). R10's only loss was the last wave: 544 one-row CTAs
// occupying a full 22.6us quantum. Fix: first 3552 rows = one-row CTAs
// (3 full waves, R10-identical); last 544 rows split into 1088 half-row CTAs
// that fill wave 4 at half duration. Per-row combine via RED slots + acq_rel
// counter, tail-only. No fences anywhere (gpu fence = CCTL.IVALL L1 flush).

#define SMOOTHING 0.1f
#define EPSILON   1e-8f
#define SUMW_CTAS 8
#define FULL_WAVE_ROWS 3552   // 3 waves x 1184 slots (148 SM x 8 CTA floor)
#define MAX_TAIL  2048

__device__ float        g_row_s[MAX_TAIL];   // split-row sum-exp partials
__device__ float        g_row_d[MAX_TAIL];   // split-row dot partials
__device__ unsigned int g_row_cnt[MAX_TAIL];
__device__ float        g_sumw;
__device__ float        g_lse_acc;
__device__ float        g_dot_acc;
__device__ float        g_gold_acc;
__device__ float        g_mask_acc;
__device__ unsigned int g_done;

// All-FMA exp (no MUFU): exp(x) = 2^(x*log2e), magic-number round,
// degree-5 poly for 2^f on [-0.5,0.5] (rel err ~2.4e-6), exponent splice.
__device__ __forceinline__ float fexp(float x) {
    float t = x * 1.4426950408889634f;
    t = fminf(fmaxf(t, -126.0f), 126.0f);
    float r = t + 12582912.0f;
    int   eb = __float_as_int(r) << 23;
    float nf = r - 12582912.0f;
    float f  = t - nf;
    float p  = 1.3333558146428443e-3f;
    p = fmaf(p, f, 9.6181291076284772e-3f);
    p = fmaf(p, f, 5.5504108664821580e-2f);
    p = fmaf(p, f, 2.4022650695910072e-1f);
    p = fmaf(p, f, 6.9314718055994531e-1f);
    p = fmaf(p, f, 1.0f);
    return __int_as_float(__float_as_int(p) + eb);
}

__device__ __forceinline__ float warp_sum(float v) {
    #pragma unroll
    for (int o = 16; o > 0; o >>= 1) v += __shfl_xor_sync(0xffffffffu, v, o);
    return v;
}

// acq_rel counter bump: release publishes this thread's prior REDs; acquire on
// the winning bump makes the peer's REDs visible. Fine-grained, no L1 flush.
__device__ __forceinline__ unsigned int atom_inc_acqrel(unsigned int* p) {
    unsigned int old;
    asm volatile("atom.acq_rel.gpu.global.add.u32 %0, [%1], 1;"
                 : "=r"(old) : "l"(p) : "memory");
    return old;
}

__device__ __forceinline__ void arrive_and_maybe_finalize(
    float* __restrict__ out, int C, unsigned int total_ctas)
{
    unsigned int prev = atom_inc_acqrel(&g_done);
    if (prev == total_ctas - 1u) {
        float sumw = __ldcg(&g_sumw);
        float lse  = __ldcg(&g_lse_acc);
        float dot  = __ldcg(&g_dot_acc);
        float gld  = __ldcg(&g_gold_acc);
        float msk  = __ldcg(&g_mask_acc);

        const float uniform = SMOOTHING / (float)(C - 1);
        const float conf    = 1.0f - SMOOTHING;
        const float cmu     = conf - uniform;
        float loss_sum = uniform * fmaf(sumw, lse, -dot) + cmu * gld;
        out[0] = loss_sum / (msk + EPSILON);

        __stcg(&g_sumw, 0.0f);
        __stcg(&g_lse_acc, 0.0f);
        __stcg(&g_dot_acc, 0.0f);
        __stcg(&g_gold_acc, 0.0f);
        __stcg(&g_mask_acc, 0.0f);
        unsigned int z = 0u;
        asm volatile("st.global.cg.u32 [%0], %1;" :: "l"(&g_done), "r"(z) : "memory");
    }
}

// Row epilogue: gold gather + 4 global REDs (shared by both CTA kinds).
__device__ __forceinline__ void emit_row(
    const float* __restrict__ logits, const int* __restrict__ gold,
    const int* __restrict__ mask, const float* __restrict__ weight,
    int row, int C, float stot, float dtot)
{
    if (mask[row] != 0) {
        int   g   = gold[row];
        float xg  = __ldg(logits + (size_t)row * C + (size_t)g);
        float wg  = __ldg(weight + g);
        float lse = logf(stot);
        atomicAdd(&g_lse_acc,  lse);
        atomicAdd(&g_dot_acc,  dtot);
        atomicAdd(&g_gold_acc, wg * (lse - xg));
        atomicAdd(&g_mask_acc, 1.0f);
    }
}

// Grid = FULL + 2*TAIL + SUMW_CTAS, where FULL = N - TAIL.
// bids [0, FULL):            one full row each (R10-identical path).
// bids [FULL, FULL+2*TAIL):  half-row each; pairs combine via RED slots.
// last SUMW_CTAS:            weight slices into g_sumw.
__global__ __launch_bounds__(256) void row_loss_kernel(
    const float* __restrict__ logits,
    const int*   __restrict__ gold,
    const int*   __restrict__ mask,
    const float* __restrict__ weight,
    float* __restrict__ out,
    int C4, int C, int N, int FULL, int TAIL)
{
    const int bid = blockIdx.x;
    const int tid = threadIdx.x;
    const float4* wp = reinterpret_cast<const float4*>(weight);
    const unsigned int total_ctas = (unsigned int)(FULL + 2 * TAIL + SUMW_CTAS);

    __shared__ float sh_s[8], sh_d[8];
    const int wid = tid >> 5;
    const int lid = tid & 31;

    if (bid >= FULL + 2 * TAIL) {
        // ---- sumW slice CTA ----
        const int slice = bid - (FULL + 2 * TAIL);
        const int per   = (C4 + SUMW_CTAS - 1) / SUMW_CTAS;
        const int lo    = slice * per;
        const int hi    = min(lo + per, C4);
        float w = 0.0f;
        for (int i = lo + tid; i < hi; i += 256) {
            float4 v = __ldg(wp + i);
            w += v.x + v.y + v.z + v.w;
        }
        w = warp_sum(w);
        if (lid == 0) sh_s[wid] = w;
        __syncthreads();
        if (tid == 0) {
            float ww = 0.0f;
            #pragma unroll
            for (int k = 0; k < 8; k++) ww += sh_s[k];
            atomicAdd(&g_sumw, ww);
            arrive_and_maybe_finalize(out, C, total_ctas);
        }
        return;
    }

    // Work extent: full row or half row.
    int row, base, len;
    if (bid < FULL) {
        row = bid; base = 0; len = C4;
    } else {
        const int idx  = bid - FULL;          // 0 .. 2*TAIL-1
        const int lrow = idx >> 1;
        row  = FULL + lrow;
        base = (idx & 1) * (C4 >> 1);
        len  = C4 >> 1;
    }

    const float4* lp = reinterpret_cast<const float4*>(logits) + (size_t)row * C4 + base;
    const float4* wh = wp + base;

    // proven streaming loop body (do not touch)
    float s = 0.0f, d = 0.0f;
    #pragma unroll 4
    for (int i = tid; i < len; i += 256) {
        float4 x = __ldcs(lp + i);
        float4 w = __ldg(wh + i);
        d = fmaf(x.x, w.x, d);
        d = fmaf(x.y, w.y, d);
        d = fmaf(x.z, w.z, d);
        d = fmaf(x.w, w.w, d);
        s += fexp(x.x);
        s += fexp(x.y);
        s += fexp(x.z);
        s += fexp(x.w);
    }

    s = warp_sum(s);
    d = warp_sum(d);
    if (lid == 0) { sh_s[wid] = s; sh_d[wid] = d; }
    __syncthreads();

    if (tid == 0) {
        float ss = 0.0f, dd = 0.0f;
        #pragma unroll
        for (int k = 0; k < 8; k++) { ss += sh_s[k]; dd += sh_d[k]; }

        if (bid < FULL) {
            emit_row(logits, gold, mask, weight, row, C, ss, dd);
        } else {
            const int lrow = (bid - FULL) >> 1;
            atomicAdd(&g_row_s[lrow], ss);
            atomicAdd(&g_row_d[lrow], dd);
            unsigned int prev = atom_inc_acqrel(&g_row_cnt[lrow]);
            if (prev == 1u) {   // second arriver owns the row
                float stot = __ldcg(&g_row_s[lrow]);
                float dtot = __ldcg(&g_row_d[lrow]);
                __stcg(&g_row_s[lrow], 0.0f);     // reset for next replay
                __stcg(&g_row_d[lrow], 0.0f);
                unsigned int z = 0u;
                asm volatile("st.global.cg.u32 [%0], %1;"
                             :: "l"(&g_row_cnt[lrow]), "r"(z) : "memory");
                emit_row(logits, gold, mask, weight, row, C, stot, dtot);
            }
        }
        arrive_and_maybe_finalize(out, C, total_ctas);
    }
}

extern "C" void kernel_launch(void* const* d_in, const int* in_sizes, int n_in,
                              void* d_out, int out_size)
{
    const float* logits = (const float*)d_in[0];
    const int*   gold   = (const int*)d_in[1];
    const int*   mask   = (const int*)d_in[2];
    const float* weight = (const float*)d_in[3];
    float*       out    = (float*)d_out;

    const int N = in_sizes[1];     // B*S rows
    const int C = in_sizes[3];     // classes
    const int C4 = C / 4;

    int TAIL = N - FULL_WAVE_ROWS;           // rows to split in half
    if (TAIL < 0) TAIL = 0;
    if (TAIL > MAX_TAIL) TAIL = MAX_TAIL;
    const int FULL = N - TAIL;

    const int grid = FULL + 2 * TAIL + SUMW_CTAS;
    row_loss_kernel<<<grid, 256>>>(logits, gold, mask, weight, out, C4, C, N, FULL, TAIL);
}

// round 15
// speedup vs baseline: 1.1099x; 1.1099x over previous
#include <cuda_runtime.h>
#include <cuda_bf16.h>

// Seq2SeqLoss: label-smoothed weighted cross-entropy, mean over masked rows.
// Harness canonical dtypes:
//   [0] outputs  f32 [B*S*C] = 131072000
//   [1] gold     i32 [B*S]   = 4096
//   [2] mask     i32 [B*S]   = 4096
//   [3] weight   f32 [C]     = 32000
// output: f32 scalar
//
// Sum factorization: with lse_r = log(sum_c exp(x_rc)), dd_r = sum_c w_c x_rc,
//   sum_r loss_r = uniform*(sumW*Σlse − Σdd) + (conf−uniform)*Σ w_g (lse − x_g)
//
// Schedule history: one-CTA-per-full-row is the only efficient decomposition
// (R11-R14 all regressed). R10's 13% loss is wave quantization:
// W = 4096/1184 = 3.46 waves -> pay 4. R15 keeps one-row-per-CTA but uses
// 512-thread CTAs (4/SM): concurrency 592 -> W = 6.92 waves -> 1.2% waste.
// Same 2048 threads/SM, same per-thread work shape, same streaming body.

#define SMOOTHING 0.1f
#define EPSILON   1e-8f
#define SUMW_CTAS 8
#define NTHREADS  512

__device__ float        g_sumw;
__device__ float        g_lse_acc;
__device__ float        g_dot_acc;
__device__ float        g_gold_acc;
__device__ float        g_mask_acc;
__device__ unsigned int g_done;

// All-FMA exp (no MUFU): exp(x) = 2^(x*log2e), magic-number round,
// degree-5 poly for 2^f on [-0.5,0.5] (rel err ~2.4e-6), exponent splice.
__device__ __forceinline__ float fexp(float x) {
    float t = x * 1.4426950408889634f;
    t = fminf(fmaxf(t, -126.0f), 126.0f);
    float r = t + 12582912.0f;
    int   eb = __float_as_int(r) << 23;
    float nf = r - 12582912.0f;
    float f  = t - nf;
    float p  = 1.3333558146428443e-3f;
    p = fmaf(p, f, 9.6181291076284772e-3f);
    p = fmaf(p, f, 5.5504108664821580e-2f);
    p = fmaf(p, f, 2.4022650695910072e-1f);
    p = fmaf(p, f, 6.9314718055994531e-1f);
    p = fmaf(p, f, 1.0f);
    return __int_as_float(__float_as_int(p) + eb);
}

__device__ __forceinline__ float warp_sum(float v) {
    #pragma unroll
    for (int o = 16; o > 0; o >>= 1) v += __shfl_xor_sync(0xffffffffu, v, o);
    return v;
}

// acq_rel counter bump: release publishes this CTA's prior REDs; acquire on
// the final bump makes all CTAs' REDs visible. No fences -> no CCTL.IVALL.
__device__ __forceinline__ unsigned int atom_inc_acqrel(unsigned int* p) {
    unsigned int old;
    asm volatile("atom.acq_rel.gpu.global.add.u32 %0, [%1], 1;"
                 : "=r"(old) : "l"(p) : "memory");
    return old;
}

__device__ __forceinline__ void arrive_and_maybe_finalize(
    float* __restrict__ out, int C, unsigned int total_ctas)
{
    unsigned int prev = atom_inc_acqrel(&g_done);
    if (prev == total_ctas - 1u) {
        float sumw = __ldcg(&g_sumw);
        float lse  = __ldcg(&g_lse_acc);
        float dot  = __ldcg(&g_dot_acc);
        float gld  = __ldcg(&g_gold_acc);
        float msk  = __ldcg(&g_mask_acc);

        const float uniform = SMOOTHING / (float)(C - 1);
        const float conf    = 1.0f - SMOOTHING;
        const float cmu     = conf - uniform;
        float loss_sum = uniform * fmaf(sumw, lse, -dot) + cmu * gld;
        out[0] = loss_sum / (msk + EPSILON);

        // reset for next graph replay (deterministic)
        __stcg(&g_sumw, 0.0f);
        __stcg(&g_lse_acc, 0.0f);
        __stcg(&g_dot_acc, 0.0f);
        __stcg(&g_gold_acc, 0.0f);
        __stcg(&g_mask_acc, 0.0f);
        unsigned int z = 0u;
        asm volatile("st.global.cg.u32 [%0], %1;" :: "l"(&g_done), "r"(z) : "memory");
    }
}

// Grid = N + SUMW_CTAS, 512 threads each.
// CTAs [0, N):   one FULL row each — proven streaming body, 16-warp reduce,
//                post-loop gold gather + 4 scalar REDs.
// CTAs [N, +8):  weight slices into g_sumw (in the shadow).
__global__ __launch_bounds__(NTHREADS, 4) void row_loss_kernel(
    const float* __restrict__ logits,
    const int*   __restrict__ gold,
    const int*   __restrict__ mask,
    const float* __restrict__ weight,
    float* __restrict__ out,
    int C4, int C, int N)
{
    const int bid = blockIdx.x;
    const int tid = threadIdx.x;
    const float4* wp = reinterpret_cast<const float4*>(weight);
    const unsigned int total_ctas = (unsigned int)(N + SUMW_CTAS);

    __shared__ float sh_s[16], sh_d[16];
    const int wid = tid >> 5;
    const int lid = tid & 31;

    if (bid >= N) {
        // ---- sumW slice CTA ----
        const int slice = bid - N;
        const int per   = (C4 + SUMW_CTAS - 1) / SUMW_CTAS;
        const int lo    = slice * per;
        const int hi    = min(lo + per, C4);
        float w = 0.0f;
        for (int i = lo + tid; i < hi; i += NTHREADS) {
            float4 v = __ldg(wp + i);
            w += v.x + v.y + v.z + v.w;
        }
        w = warp_sum(w);
        if (lid == 0) sh_s[wid] = w;
        __syncthreads();
        if (tid == 0) {
            float ww = 0.0f;
            #pragma unroll
            for (int k = 0; k < 16; k++) ww += sh_s[k];
            atomicAdd(&g_sumw, ww);
            arrive_and_maybe_finalize(out, C, total_ctas);
        }
        return;
    }

    // ---- row CTA: proven streaming loop body (512-thread stride) ----
    const int row = bid;
    const float4* lp = reinterpret_cast<const float4*>(logits) + (size_t)row * C4;

    float s = 0.0f, d = 0.0f;
    #pragma unroll 4
    for (int i = tid; i < C4; i += NTHREADS) {
        float4 x = __ldcs(lp + i);
        float4 w = __ldg(wp + i);
        d = fmaf(x.x, w.x, d);
        d = fmaf(x.y, w.y, d);
        d = fmaf(x.z, w.z, d);
        d = fmaf(x.w, w.w, d);
        s += fexp(x.x);
        s += fexp(x.y);
        s += fexp(x.z);
        s += fexp(x.w);
    }

    s = warp_sum(s);
    d = warp_sum(d);
    if (lid == 0) { sh_s[wid] = s; sh_d[wid] = d; }
    __syncthreads();

    if (tid == 0) {
        if (mask[row] != 0) {
            float ss = 0.0f, dd = 0.0f;
            #pragma unroll
            for (int k = 0; k < 16; k++) { ss += sh_s[k]; dd += sh_d[k]; }

            int   g   = gold[row];
            float xg  = __ldg(logits + (size_t)row * C + (size_t)g);
            float wg  = __ldg(weight + g);
            float lse = logf(ss);

            atomicAdd(&g_lse_acc,  lse);
            atomicAdd(&g_dot_acc,  dd);
            atomicAdd(&g_gold_acc, wg * (lse - xg));
            atomicAdd(&g_mask_acc, 1.0f);
        }
        arrive_and_maybe_finalize(out, C, total_ctas);
    }
}

extern "C" void kernel_launch(void* const* d_in, const int* in_sizes, int n_in,
                              void* d_out, int out_size)
{
    const float* logits = (const float*)d_in[0];
    const int*   gold   = (const int*)d_in[1];
    const int*   mask   = (const int*)d_in[2];
    const float* weight = (const float*)d_in[3];
    float*       out    = (float*)d_out;

    const int N = in_sizes[1];     // B*S rows
    const int C = in_sizes[3];     // classes
    const int C4 = C / 4;

    row_loss_kernel<<<N + SUMW_CTAS, NTHREADS>>>(logits, gold, mask, weight, out, C4, C, N);
}